// round 5
// baseline (speedup 1.0000x reference)
#include <cuda_runtime.h>
#include <math.h>

#define UNITS 1536
#define NZ 6144                 // 4*UNITS gate pre-activations
#define NSPLIT 128              // k-splits per GEMV
#define TPB 256                 // threads per block (1024 cols per block)
#define XTILES 6                // 6144 / 1024
#define WPS (XTILES * NSPLIT)   // worker blocks per matrix slab = 768
#define CHAR_LEN 256
#define VOCAB 80
#define N_MIX 10
#define KA1 (3 + VOCAB)         // 83
#define KX  (3 + VOCAB + UNITS) // 1619

// ---------------- device scratch (no allocations allowed) ----------------
__device__ float g_part1[NSPLIT * NZ];  // chain partials (W1+U1, then W2, then W3)
__device__ float g_part2[NSPLIT * NZ];  // U2 @ h2 partials
__device__ float g_part3[NSPLIT * NZ];  // U3 @ h3 partials
__device__ float g_coefpart[48][30];    // h1n @ Wd partials (from gates1 blocks)
__device__ float g_x2[KX];              // [inputs, w, h1n]
__device__ float g_x3[KX];              // [inputs, w, h2n]
__device__ int g_cA, g_cB, g_cC, g_cD, g_cE, g_cF;   // spin counters (reset each call)

__device__ __forceinline__ float sigf(float x) { return 1.0f / (1.0f + expf(-x)); }

struct Seg { const float* M; const float* x; int K; };

// ---------------- split-K GEMV worker --------------------------------------
// Stage x values + per-row matrix pointers in smem (segment logic runs once),
// then a branch-free inner loop: 8 independent LDG.128 per batch.
__device__ __forceinline__ void gemv3(
    Seg s0, Seg s1, Seg s2, int Ktot, int xt, int split, float* __restrict__ part)
{
    __shared__ float xs[16];
    __shared__ const float* rowp[16];
    int t = threadIdx.x;
    int k0 = (Ktot * split) / NSPLIT;
    int k1 = (Ktot * (split + 1)) / NSPLIT;
    int len = k1 - k0;                       // <= 13
    if (t < len) {
        int k = k0 + t;
        if (k < s0.K)             { xs[t] = __ldg(s0.x + k);            rowp[t] = s0.M + (size_t)k * NZ; }
        else if (k < s0.K + s1.K) { int kk = k - s0.K;  xs[t] = __ldg(s1.x + kk); rowp[t] = s1.M + (size_t)kk * NZ; }
        else                      { int kk = k - s0.K - s1.K; xs[t] = __ldg(s2.x + kk); rowp[t] = s2.M + (size_t)kk * NZ; }
    }
    __syncthreads();

    int col4 = (xt * TPB + t) * 4;
    float4 acc = make_float4(0.f, 0.f, 0.f, 0.f);
    int k = 0;
    for (; k + 8 <= len; k += 8) {
        float xv[8]; float4 r[8];
        #pragma unroll
        for (int i = 0; i < 8; ++i) {
            xv[i] = xs[k + i];
            r[i] = *reinterpret_cast<const float4*>(rowp[k + i] + col4);
        }
        #pragma unroll
        for (int i = 0; i < 8; ++i) {
            acc.x += xv[i] * r[i].x; acc.y += xv[i] * r[i].y;
            acc.z += xv[i] * r[i].z; acc.w += xv[i] * r[i].w;
        }
    }
    if (k + 4 <= len) {
        float xv[4]; float4 r[4];
        #pragma unroll
        for (int i = 0; i < 4; ++i) {
            xv[i] = xs[k + i];
            r[i] = *reinterpret_cast<const float4*>(rowp[k + i] + col4);
        }
        #pragma unroll
        for (int i = 0; i < 4; ++i) {
            acc.x += xv[i] * r[i].x; acc.y += xv[i] * r[i].y;
            acc.z += xv[i] * r[i].z; acc.w += xv[i] * r[i].w;
        }
        k += 4;
    }
    for (; k < len; ++k) {
        float xv = xs[k];
        float4 r = *reinterpret_cast<const float4*>(rowp[k] + col4);
        acc.x += xv * r.x; acc.y += xv * r.y; acc.z += xv * r.z; acc.w += xv * r.w;
    }
    *reinterpret_cast<float4*>(part + (size_t)split * NZ + col4) = acc;
}

// ---------------- gates: reduce partials + LSTM nonlinearity ----------------
__device__ __forceinline__ void gates_body(
    int blk, const float* __restrict__ b, const float* __restrict__ c_in,
    const float* __restrict__ pA, const float* __restrict__ pB,
    float* __restrict__ out_h, float* __restrict__ xnext,
    const float* __restrict__ Wd)
{
    __shared__ float red[8][32][4];
    __shared__ float hsh[32];
    __shared__ float csh[4][30];
    int t = threadIdx.x, ul = t & 31, sg = t >> 5;   // 8 subgroups
    int u = blk * 32 + ul;

    float s0 = 0.f, s1 = 0.f, s2 = 0.f, s3 = 0.f;
    #pragma unroll
    for (int i = 0; i < NSPLIT / 8; ++i) {
        const float* row = pA + (size_t)(sg + i * 8) * NZ;
        s0 += row[u]; s1 += row[u + UNITS]; s2 += row[u + 2 * UNITS]; s3 += row[u + 3 * UNITS];
    }
    if (pB) {
        #pragma unroll
        for (int i = 0; i < NSPLIT / 8; ++i) {
            const float* row = pB + (size_t)(sg + i * 8) * NZ;
            s0 += row[u]; s1 += row[u + UNITS]; s2 += row[u + 2 * UNITS]; s3 += row[u + 3 * UNITS];
        }
    }
    red[sg][ul][0] = s0; red[sg][ul][1] = s1; red[sg][ul][2] = s2; red[sg][ul][3] = s3;
    __syncthreads();

    if (sg == 0) {
        float zi = b[u], zf = b[u + UNITS], zg = b[u + 2 * UNITS], zo = b[u + 3 * UNITS];
        #pragma unroll
        for (int g = 0; g < 8; ++g) {
            zi += red[g][ul][0]; zf += red[g][ul][1];
            zg += red[g][ul][2]; zo += red[g][ul][3];
        }
        float c = sigf(zf) * c_in[u] + sigf(zi) * tanhf(zg);
        float h = sigf(zo) * tanhf(c);
        out_h[u] = h;
        if (xnext) xnext[u] = h;
        hsh[ul] = h;
    }

    if (Wd) {
        __syncthreads();
        if (t < 120) {                       // j = t%30, unit-group g = t/30 (8 units)
            int j = t % 30, g = t / 30;
            int ub = blk * 32 + g * 8;
            float s = 0.f;
            #pragma unroll
            for (int i = 0; i < 8; ++i)
                s += hsh[g * 8 + i] * __ldg(Wd + (size_t)(ub + i) * 30 + j);
            csh[g][j] = s;
        }
        __syncthreads();
        if (t < 30)
            g_coefpart[blk][t] = csh[0][t] + csh[1][t] + csh[2][t] + csh[3][t];
    }
}

// ---------------- window finisher (256 threads) ------------------------------
__device__ __forceinline__ void window_body(
    const float* __restrict__ bd, const float* __restrict__ kp,
    const float* __restrict__ sentence, const float* __restrict__ inputs)
{
    __shared__ float coef[30];
    __shared__ float alpha[N_MIX], beta[N_MIX], kap[N_MIX];
    __shared__ float phi[CHAR_LEN];
    __shared__ float wpart[8][VOCAB];
    int t = threadIdx.x, warp = t >> 5, lane = t & 31;

    if (t < 3) { g_x2[t] = inputs[t]; g_x3[t] = inputs[t]; }
    if (t < 30) {
        float s = bd[t];
        #pragma unroll
        for (int blk = 0; blk < 48; ++blk) s += g_coefpart[blk][t];
        coef[t] = s;
    }
    __syncthreads();
    if (t < N_MIX) {
        alpha[t] = expf(coef[t]);
        beta[t]  = expf(coef[N_MIX + t]);
        kap[t]   = kp[t] + expf(coef[2 * N_MIX + t]);
    }
    __syncthreads();
    {
        float u = (float)(t + 1);
        float p = 0.f;
        #pragma unroll
        for (int m = 0; m < N_MIX; ++m) {
            float d = kap[m] - u;
            p += alpha[m] * expf(-beta[m] * d * d);
        }
        phi[t] = p;                           // t covers 0..255 exactly
    }
    __syncthreads();
    {
        float a0 = 0.f, a1 = 0.f, a2 = 0.f;
        #pragma unroll 8
        for (int cc = 0; cc < 32; ++cc) {
            int c = warp * 32 + cc;
            float pv = phi[c];
            const float* row = sentence + (size_t)c * VOCAB;
            a0 += pv * __ldg(row + lane);
            a1 += pv * __ldg(row + 32 + lane);
            if (lane < 16) a2 += pv * __ldg(row + 64 + lane);
        }
        wpart[warp][lane]      = a0;
        wpart[warp][lane + 32] = a1;
        if (lane < 16) wpart[warp][lane + 64] = a2;
    }
    __syncthreads();
    if (t < VOCAB) {
        float s = 0.f;
        #pragma unroll
        for (int w = 0; w < 8; ++w) s += wpart[w][t];
        g_x2[3 + t] = s;
        g_x3[3 + t] = s;
    }
}

// ---------------- fused launch A: mega GEMV + gates1 + coef + window --------
__global__ void __launch_bounds__(TPB) fusedA(
    const float* __restrict__ W1, const float* __restrict__ inputs,
    const float* __restrict__ wprev, const float* __restrict__ U1, const float* __restrict__ h1,
    const float* __restrict__ U2, const float* __restrict__ h2,
    const float* __restrict__ U3, const float* __restrict__ h3,
    const float* __restrict__ b1, const float* __restrict__ c1, float* __restrict__ out,
    const float* __restrict__ Wd, const float* __restrict__ bd,
    const float* __restrict__ kappa_prev, const float* __restrict__ sentence)
{
    int bid = blockIdx.x;
    if (bid < 3 * WPS) {
        int slab = bid / WPS, r = bid % WPS;
        int xt = r % XTILES, split = r / XTILES;
        Seg z = {nullptr, nullptr, 0};
        if (slab == 0) {
            gemv3(Seg{W1, inputs, 3}, Seg{W1 + (size_t)3 * NZ, wprev, VOCAB},
                  Seg{U1, h1, UNITS}, KX, xt, split, g_part1);
            __syncthreads();
            if (threadIdx.x == 0) { __threadfence(); atomicAdd(&g_cA, 1); }
        } else if (slab == 1) {
            gemv3(Seg{U2, h2, UNITS}, z, z, UNITS, xt, split, g_part2);
        } else {
            gemv3(Seg{U3, h3, UNITS}, z, z, UNITS, xt, split, g_part3);
        }
    } else if (bid < 3 * WPS + 48) {
        int blk = bid - 3 * WPS;
        if (threadIdx.x == 0) { while (((volatile int*)&g_cA)[0] < WPS) __nanosleep(32); }
        __syncthreads(); __threadfence();
        gates_body(blk, b1, c1, g_part1, nullptr, out, g_x2 + KA1, Wd);
        __syncthreads();
        if (threadIdx.x == 0) { __threadfence(); atomicAdd(&g_cB, 1); }
    } else {
        if (threadIdx.x == 0) { while (((volatile int*)&g_cB)[0] < 48) __nanosleep(32); }
        __syncthreads(); __threadfence();
        window_body(bd, kappa_prev, sentence, inputs);
        __syncthreads();
        if (threadIdx.x == 0) { g_cA = 0; g_cB = 0; __threadfence(); }
    }
}

// ---------------- fused launch B/C: chain GEMV + gates ----------------------
__global__ void __launch_bounds__(TPB) fusedChain(
    const float* __restrict__ W, const float* __restrict__ x,
    const float* __restrict__ pB,
    const float* __restrict__ b, const float* __restrict__ c_in,
    float* __restrict__ out_h, float* __restrict__ xnext,
    int* __restrict__ cW, int* __restrict__ cG)
{
    int bid = blockIdx.x;
    if (bid < WPS) {
        int xt = bid % XTILES, split = bid / XTILES;
        Seg z = {nullptr, nullptr, 0};
        gemv3(Seg{W, x, KX}, z, z, KX, xt, split, g_part1);
        __syncthreads();
        if (threadIdx.x == 0) { __threadfence(); atomicAdd(cW, 1); }
    } else {
        int blk = bid - WPS;
        if (threadIdx.x == 0) { while (((volatile int*)cW)[0] < WPS) __nanosleep(32); }
        __syncthreads(); __threadfence();
        gates_body(blk, b, c_in, g_part1, pB, out_h, xnext, nullptr);
        __syncthreads();
        if (threadIdx.x == 0) {
            __threadfence();
            int v = atomicAdd(cG, 1);
            if (v == 47) { *cW = 0; *cG = 0; __threadfence(); }
        }
    }
}

// ---------------- launch ----------------
extern "C" void kernel_launch(void* const* d_in, const int* in_sizes, int n_in,
                              void* d_out, int out_size)
{
    const float* inputs     = (const float*)d_in[0];
    const float* h1_in      = (const float*)d_in[1];
    const float* c1_in      = (const float*)d_in[2];
    const float* h2_in      = (const float*)d_in[3];
    const float* c2_in      = (const float*)d_in[4];
    const float* h3_in      = (const float*)d_in[5];
    const float* c3_in      = (const float*)d_in[6];
    const float* w_prev     = (const float*)d_in[7];
    const float* kappa_prev = (const float*)d_in[8];
    const float* sentence   = (const float*)d_in[9];
    const float* W1 = (const float*)d_in[10];
    const float* U1 = (const float*)d_in[11];
    const float* b1 = (const float*)d_in[12];
    const float* Wd = (const float*)d_in[13];
    const float* bd = (const float*)d_in[14];
    const float* W2 = (const float*)d_in[15];
    const float* U2 = (const float*)d_in[16];
    const float* b2 = (const float*)d_in[17];
    const float* W3 = (const float*)d_in[18];
    const float* U3 = (const float*)d_in[19];
    const float* b3 = (const float*)d_in[20];
    float* out = (float*)d_out;

    float *x2p, *x3p, *p2p, *p3p;
    cudaGetSymbolAddress((void**)&x2p, g_x2);
    cudaGetSymbolAddress((void**)&x3p, g_x3);
    cudaGetSymbolAddress((void**)&p2p, g_part2);
    cudaGetSymbolAddress((void**)&p3p, g_part3);
    int *cCp, *cDp, *cEp, *cFp;
    cudaGetSymbolAddress((void**)&cCp, g_cC);
    cudaGetSymbolAddress((void**)&cDp, g_cD);
    cudaGetSymbolAddress((void**)&cEp, g_cE);
    cudaGetSymbolAddress((void**)&cFp, g_cF);

    // Launch A: mega GEMV (W1+U1 -> part1, U2@h2 -> part2, U3@h3 -> part3)
    // + fused gates1 (+coef partials) + window finisher via spin barriers.
    fusedA<<<3 * WPS + 49, TPB>>>(W1, inputs, w_prev, U1, h1_in,
                                  U2, h2_in, U3, h3_in,
                                  b1, c1_in, out, Wd, bd, kappa_prev, sentence);

    // Launch B: W2 @ x2 -> part1 ; gates2 reduces part1 + part2.
    fusedChain<<<WPS + 48, TPB>>>(W2, x2p, p2p, b2, c2_in,
                                  out + UNITS, x3p + KA1, cCp, cDp);

    // Launch C: W3 @ x3 -> part1 ; gates3 reduces part1 + part3.
    fusedChain<<<WPS + 48, TPB>>>(W3, x3p, p3p, b3, c3_in,
                                  out + 2 * UNITS, nullptr, cEp, cFp);
}